// round 11
// baseline (speedup 1.0000x reference)
#include <cuda_runtime.h>
#include <cuda_fp16.h>
#include <cstdint>

// out[m,n] = relu( sum_k x[m,k] * W[n,k] + b[n] )
// M=131072, N=256, K=256 fp32 in/out.
// fp16 mma.sync m16n8k16. B (all of W, fp16) resident in smem, loaded once.
// A loaded per-lane via LDG.64 + cvt directly into MMA fragments.
// ZERO mainloop barriers: 16 warps fully decoupled.

#define BM    128
#define NDIM  256
#define KDIM  256
#define CHUNKB 32768                      // one K64-chunk of B: 256 rows x 128B
#define SMEM_BYTES (4 * CHUNKB)           // 128 KB: full B resident

__device__ __half g_Wh[NDIM * KDIM];      // 128 KB fp16 W

__global__ void convW_kernel(const float* __restrict__ W) {
    int i = blockIdx.x * 1024 + threadIdx.x;   // 64 x 1024
    g_Wh[i] = __float2half_rn(W[i]);
}

__device__ __forceinline__ uint32_t pack_h2(float lo, float hi) {
    uint32_t d;
    asm("cvt.rn.f16x2.f32 %0, %1, %2;" : "=r"(d) : "f"(hi), "f"(lo));
    return d;
}
__device__ __forceinline__ void ldsm_x4(uint32_t* r, uint32_t addr) {
    asm volatile("ldmatrix.sync.aligned.m8n8.x4.shared.b16 {%0,%1,%2,%3}, [%4];"
                 : "=r"(r[0]), "=r"(r[1]), "=r"(r[2]), "=r"(r[3]) : "r"(addr));
}

__global__ void __launch_bounds__(512, 1)
gemm_f16_residentB(const float* __restrict__ X, const float* __restrict__ bias,
                   float* __restrict__ Out)
{
    extern __shared__ char smem[];
    const uint32_t sB = (uint32_t)__cvta_generic_to_shared(smem);

    const int tid  = threadIdx.x;
    const int lane = tid & 31;
    const int warp = tid >> 5;          // 0..15
    const int warpM = warp & 3;         // 4 x 32-row M slices
    const int warpN = warp >> 2;        // 4 x 64-col N slices
    const int ctaM = blockIdx.x * BM;

    const int j   = lane & 7;
    const int mat = lane >> 3;

    // ---- load ALL of B (4 K64-chunks, SW128 layout) once ----
#pragma unroll
    for (int ch = 0; ch < 4; ch++) {
#pragma unroll
        for (int i = 0; i < 4; i++) {              // 256 rows x 8 x 16B = 2048
            int s = tid + i * 512;
            int row = s >> 3, u16 = s & 7;
            uint32_t dst = sB + ch * CHUNKB + row * 128 + ((u16 ^ (row & 7)) << 4);
            const __half* src = g_Wh + (size_t)row * KDIM + ch * 64 + u16 * 8;
            asm volatile("cp.async.cg.shared.global [%0], [%1], 16;"
                         :: "r"(dst), "l"(src));
        }
    }
    asm volatile("cp.async.commit_group;" ::: "memory");

    // B LDSM base offsets (within a chunk): per n16-pair p
    // mat0=n0-7/kg0, mat1=n0-7/kg1, mat2=n8-15/kg0, mat3=n8-15/kg1
    uint32_t bOff[4];
#pragma unroll
    for (int p = 0; p < 4; p++) {
        const int brow = warpN * 64 + p * 16 + (mat >> 1) * 8 + j;
        bOff[p] = (uint32_t)(brow * 128 + (((mat & 1) ^ j) << 4));
    }

    // A per-lane gmem pointers: lane holds rows (l>>2) and (l>>2)+8 of each m16 tile,
    // k-pairs at 2*(l&3) and 2*(l&3)+8
    const int r4 = lane >> 2, c4 = lane & 3;
    const float* aRow0 = X + (size_t)(ctaM + warpM * 32 + r4) * KDIM + 2 * c4;
    // offsets: +0 (a0), +8*K (a1), +8 (a2), +8*K+8 (a3); mt adds 16*K

    float acc[2][8][4];
#pragma unroll
    for (int i = 0; i < 2; i++)
#pragma unroll
        for (int jj = 0; jj < 8; jj++)
#pragma unroll
            for (int q = 0; q < 4; q++) acc[i][jj][q] = 0.0f;

    asm volatile("cp.async.wait_group 0;" ::: "memory");
    __syncthreads();                    // ONLY barrier in the kernel body

    // ---- mainloop: 16 k16-steps, no barriers, fully unrolled ----
#pragma unroll
    for (int ks = 0; ks < 16; ks++) {
        const int kbase = ks * 16;
        // A fragments: LDG.64 + cvt in registers
        uint32_t a[2][4];
#pragma unroll
        for (int mt = 0; mt < 2; mt++) {
            const float* ap = aRow0 + (size_t)mt * 16 * KDIM + kbase;
            float2 v0 = *(const float2*)(ap);
            float2 v1 = *(const float2*)(ap + 8 * KDIM);
            float2 v2 = *(const float2*)(ap + 8);
            float2 v3 = *(const float2*)(ap + 8 * KDIM + 8);
            a[mt][0] = pack_h2(v0.x, v0.y);
            a[mt][1] = pack_h2(v1.x, v1.y);
            a[mt][2] = pack_h2(v2.x, v2.y);
            a[mt][3] = pack_h2(v3.x, v3.y);
        }
        // B fragments from resident smem
        const uint32_t cbase = sB + (uint32_t)(ks >> 2) * CHUNKB;
        const uint32_t x = (uint32_t)((ks & 3) << 5);
        uint32_t b[4][4];
        ldsm_x4(b[0], (cbase + bOff[0]) ^ x);
        ldsm_x4(b[1], (cbase + bOff[1]) ^ x);
        ldsm_x4(b[2], (cbase + bOff[2]) ^ x);
        ldsm_x4(b[3], (cbase + bOff[3]) ^ x);
#pragma unroll
        for (int p = 0; p < 4; p++) {
#pragma unroll
            for (int s = 0; s < 2; s++) {
                const int nt = 2 * p + s;
#pragma unroll
                for (int mt = 0; mt < 2; mt++) {
                    asm volatile(
                        "mma.sync.aligned.m16n8k16.row.col.f32.f16.f16.f32 "
                        "{%0,%1,%2,%3}, {%4,%5,%6,%7}, {%8,%9}, {%0,%1,%2,%3};\n"
                        : "+f"(acc[mt][nt][0]), "+f"(acc[mt][nt][1]),
                          "+f"(acc[mt][nt][2]), "+f"(acc[mt][nt][3])
                        : "r"(a[mt][0]), "r"(a[mt][1]), "r"(a[mt][2]), "r"(a[mt][3]),
                          "r"(b[p][2*s]), "r"(b[p][2*s+1]));
                }
            }
        }
    }

    // ---- epilogue: bias + relu, float2 stores (no sync needed) ----
#pragma unroll
    for (int mt = 0; mt < 2; mt++) {
        const int m0 = ctaM + warpM * 32 + mt * 16 + r4;
#pragma unroll
        for (int nt = 0; nt < 8; nt++) {
            const int n0 = warpN * 64 + nt * 8 + 2 * c4;
            const float bv0 = __ldg(&bias[n0]);
            const float bv1 = __ldg(&bias[n0 + 1]);
            float v0 = fmaxf(acc[mt][nt][0] + bv0, 0.0f);
            float v1 = fmaxf(acc[mt][nt][1] + bv1, 0.0f);
            float v2 = fmaxf(acc[mt][nt][2] + bv0, 0.0f);
            float v3 = fmaxf(acc[mt][nt][3] + bv1, 0.0f);
            *(float2*)&Out[(size_t)m0 * NDIM + n0]       = make_float2(v0, v1);
            *(float2*)&Out[(size_t)(m0 + 8) * NDIM + n0] = make_float2(v2, v3);
        }
    }
}

extern "C" void kernel_launch(void* const* d_in, const int* in_sizes, int n_in,
                              void* d_out, int out_size)
{
    const float* x = (const float*)d_in[0];   // [131072, 256]
    const float* W = (const float*)d_in[1];   // [256, 256]
    const float* b = (const float*)d_in[2];   // [256]
    float* out = (float*)d_out;

    convW_kernel<<<64, 1024>>>(W);

    cudaFuncSetAttribute(gemm_f16_residentB,
                         cudaFuncAttributeMaxDynamicSharedMemorySize, SMEM_BYTES);
    dim3 grid(131072 / BM);                   // 1024 CTAs, full N per CTA
    gemm_f16_residentB<<<grid, 512, SMEM_BYTES>>>(x, b, out);
}

// round 13
// speedup vs baseline: 1.3590x; 1.3590x over previous
#include <cuda_runtime.h>
#include <cuda_fp16.h>
#include <cstdint>

// out[m,n] = relu( sum_k x[m,k] * W[n,k] + b[n] )
// M=131072, N=256, K=256 fp32 in/out.
// fp16 mma.sync m16n8k16 + ldmatrix. Persistent 148 CTAs.
// B (all of W, fp16, SW128) resident in smem for the CTA lifetime.
// A: LDG.128 -> cvt -> STS.64, double-buffered 16KB stages, 1 bar per chunk.

#define NTILES 1024
#define GRID   148
#define NDIM   256
#define KDIM   256

#define ABUF   16384                 // one A stage: 128 rows x 128B
#define CHUNKB 32768                 // one B K64-chunk: 256 rows x 128B
#define SMEM_BYTES (2 * ABUF + 4 * CHUNKB)   // 160 KB

__device__ __half g_Wh[NDIM * KDIM];

__global__ void convW_kernel(const float* __restrict__ W) {
    int i = blockIdx.x * 1024 + threadIdx.x;   // 64 x 1024
    g_Wh[i] = __float2half_rn(W[i]);
}

__device__ __forceinline__ uint32_t pack_h2(float lo, float hi) {
    uint32_t d;
    asm("cvt.rn.f16x2.f32 %0, %1, %2;" : "=r"(d) : "f"(hi), "f"(lo));
    return d;
}
__device__ __forceinline__ void ldsm_x4(uint32_t* r, uint32_t addr) {
    asm volatile("ldmatrix.sync.aligned.m8n8.x4.shared.b16 {%0,%1,%2,%3}, [%4];"
                 : "=r"(r[0]), "=r"(r[1]), "=r"(r[2]), "=r"(r[3]) : "r"(addr));
}

__global__ void __launch_bounds__(512, 1)
gemm_f16_persist(const float* __restrict__ X, const float* __restrict__ bias,
                 float* __restrict__ Out)
{
    extern __shared__ char smem[];
    const uint32_t sbase = (uint32_t)__cvta_generic_to_shared(smem);
    const uint32_t sA[2] = { sbase, sbase + ABUF };
    const uint32_t sB    = sbase + 2 * ABUF;

    const int tid  = threadIdx.x;
    const int lane = tid & 31;
    const int warp = tid >> 5;          // 0..15
    const int warpM = warp & 3;         // 4 x 32-row M slices
    const int warpN = warp >> 2;        // 4 x 64-col N slices

    const int j   = lane & 7;
    const int mat = lane >> 3;
    const int r4  = lane >> 2, c4 = lane & 3;

    // ---- load ALL of B once (4 K64 chunks, SW128) ----
#pragma unroll
    for (int i = 0; i < 16; i++) {
        int s = tid + i * 512;                  // 0..8191 granules
        int chunk = s >> 11;
        int idx = s & 2047;
        int row = idx >> 3, u16 = idx & 7;
        uint32_t dst = sB + chunk * CHUNKB + row * 128 + ((u16 ^ (row & 7)) << 4);
        const __half* src = g_Wh + (size_t)row * KDIM + chunk * 64 + u16 * 8;
        asm volatile("cp.async.cg.shared.global [%0], [%1], 16;"
                     :: "r"(dst), "l"(src));
    }
    asm volatile("cp.async.commit_group;" ::: "memory");

    // LDSM offsets
    uint32_t aOff[2];
#pragma unroll
    for (int mt = 0; mt < 2; mt++) {
        const int arow = warpM * 32 + mt * 16 + (mat & 1) * 8 + j;
        aOff[mt] = (uint32_t)(arow * 128 + (((mat >> 1) ^ j) << 4));
    }
    uint32_t bOff[4];
#pragma unroll
    for (int p = 0; p < 4; p++) {
        const int brow = warpN * 64 + p * 16 + (mat >> 1) * 8 + j;
        bOff[p] = (uint32_t)(brow * 128 + (((mat & 1) ^ j) << 4));
    }

    // ---- A prefetch registers ----
    float4 pf[4];
    auto ldgA = [&](int t, int ch) {
#pragma unroll
        for (int i = 0; i < 4; i++) {
            int f = tid + i * 512;
            int row = f >> 4, q = f & 15;
            pf[i] = __ldg((const float4*)(X + (size_t)(t * 128 + row) * KDIM + ch * 64 + q * 4));
        }
    };
    auto stsA = [&](uint32_t sAbuf) {
#pragma unroll
        for (int i = 0; i < 4; i++) {
            int f = tid + i * 512;
            int row = f >> 4, q = f & 15;       // q = 8B fp16 slot
            uint32_t h01 = pack_h2(pf[i].x, pf[i].y);
            uint32_t h23 = pack_h2(pf[i].z, pf[i].w);
            uint32_t addr = sAbuf + row * 128
                          + ((((q >> 1) ^ (row & 7)) << 4) | ((q & 1) << 3));
            asm volatile("st.shared.v2.b32 [%0], {%1, %2};"
                         :: "r"(addr), "r"(h01), "r"(h23) : "memory");
        }
    };

    // first A chunk for this CTA's first tile
    ldgA(blockIdx.x, 0);
    asm volatile("cp.async.wait_group 0;" ::: "memory");
    __syncthreads();                            // B resident + (pf in regs)

    // ---- persistent tile loop ----
#pragma unroll 1
    for (int t = blockIdx.x; t < NTILES; t += GRID) {
        float acc[2][8][4];
#pragma unroll
        for (int i = 0; i < 2; i++)
#pragma unroll
            for (int jj = 0; jj < 8; jj++)
#pragma unroll
                for (int q = 0; q < 4; q++) acc[i][jj][q] = 0.0f;

#pragma unroll
        for (int ch = 0; ch < 4; ch++) {
            const uint32_t sAbuf = sA[ch & 1];
            stsA(sAbuf);                        // chunk (t, ch)
            // prefetch next chunk (possibly next tile) before the barrier
            {
                const int nt = (ch < 3) ? t : t + GRID;
                const int nc = (ch + 1) & 3;
                if (nt < NTILES) ldgA(nt, nc);
            }
            __syncthreads();                    // A stage visible

            const uint32_t bChunk = sB + ch * CHUNKB;
#pragma unroll
            for (int ks = 0; ks < 4; ks++) {
                const uint32_t x = (uint32_t)(ks << 5);
                uint32_t a[2][4], b[4][4];
                ldsm_x4(a[0], (sAbuf + aOff[0]) ^ x);
                ldsm_x4(a[1], (sAbuf + aOff[1]) ^ x);
                ldsm_x4(b[0], (bChunk + bOff[0]) ^ x);
                ldsm_x4(b[1], (bChunk + bOff[1]) ^ x);
                ldsm_x4(b[2], (bChunk + bOff[2]) ^ x);
                ldsm_x4(b[3], (bChunk + bOff[3]) ^ x);
#pragma unroll
                for (int p = 0; p < 4; p++) {
#pragma unroll
                    for (int s = 0; s < 2; s++) {
                        const int nt2 = 2 * p + s;
#pragma unroll
                        for (int mt = 0; mt < 2; mt++) {
                            asm volatile(
                                "mma.sync.aligned.m16n8k16.row.col.f32.f16.f16.f32 "
                                "{%0,%1,%2,%3}, {%4,%5,%6,%7}, {%8,%9}, {%0,%1,%2,%3};\n"
                                : "+f"(acc[mt][nt2][0]), "+f"(acc[mt][nt2][1]),
                                  "+f"(acc[mt][nt2][2]), "+f"(acc[mt][nt2][3])
                                : "r"(a[mt][0]), "r"(a[mt][1]), "r"(a[mt][2]), "r"(a[mt][3]),
                                  "r"(b[p][2*s]), "r"(b[p][2*s+1]));
                        }
                    }
                }
            }
            // NOTE: no second barrier needed — next stsA targets the other stage,
            // and the next bar.sync orders chunk ch-2's readers before overwrite.
        }

        // ---- epilogue (registers only, no sync) ----
#pragma unroll
        for (int mt = 0; mt < 2; mt++) {
            const int m0 = t * 128 + warpM * 32 + mt * 16 + r4;
#pragma unroll
            for (int nt2 = 0; nt2 < 8; nt2++) {
                const int n0 = warpN * 64 + nt2 * 8 + 2 * c4;
                const float bv0 = __ldg(&bias[n0]);
                const float bv1 = __ldg(&bias[n0 + 1]);
                float v0 = fmaxf(acc[mt][nt2][0] + bv0, 0.0f);
                float v1 = fmaxf(acc[mt][nt2][1] + bv1, 0.0f);
                float v2 = fmaxf(acc[mt][nt2][2] + bv0, 0.0f);
                float v3 = fmaxf(acc[mt][nt2][3] + bv1, 0.0f);
                *(float2*)&Out[(size_t)m0 * NDIM + n0]       = make_float2(v0, v1);
                *(float2*)&Out[(size_t)(m0 + 8) * NDIM + n0] = make_float2(v2, v3);
            }
        }
    }
}

extern "C" void kernel_launch(void* const* d_in, const int* in_sizes, int n_in,
                              void* d_out, int out_size)
{
    const float* x = (const float*)d_in[0];   // [131072, 256]
    const float* W = (const float*)d_in[1];   // [256, 256]
    const float* b = (const float*)d_in[2];   // [256]
    float* out = (float*)d_out;

    convW_kernel<<<64, 1024>>>(W);

    cudaFuncSetAttribute(gemm_f16_persist,
                         cudaFuncAttributeMaxDynamicSharedMemorySize, SMEM_BYTES);
    gemm_f16_persist<<<GRID, 512, SMEM_BYTES>>>(x, b, out);
}